// round 10
// baseline (speedup 1.0000x reference)
#include <cuda_runtime.h>

#define NSAMP 8192
#define NOPT  16
#define DIM   768
#define NV4   (DIM / 4)      // 192 float4 per row
#define NPAIR 136            // 16*17/2 upper-triangular incl. diagonal
#define HPAIR 68             // NPAIR / 2
#define MARGIN 0.3f
#define NEG_INF -1e9f

// Deterministic per-sample scratch (no device-side allocation allowed).
__device__ float g_loss[NSAMP];
__device__ float g_cnt[NSAMP];

__device__ __forceinline__ constexpr int triu_idx(int n, int m) {
    // n <= m required. Pairs of row n start at 16n - n(n-1)/2.
    return n * 16 - (n * (n - 1)) / 2 + (m - n);
}

// One warp per sample. Lane l owns float4 chunks at index l + 32c (c = 0..5).
// Each lane accumulates all 136 pair partial dot-products in registers
// (4 FMAs per pair per chunk from the float4 components), then a merged
// butterfly reduces two pairs per 5-level tree across lanes.
__global__ __launch_bounds__(128, 2)
void gram_kernel(const float4* __restrict__ emb, const int* __restrict__ labels)
{
    const int warp = threadIdx.x >> 5;
    const int lane = threadIdx.x & 31;
    const int sample = blockIdx.x * 4 + warp;

    const float4* base = emb + (size_t)sample * (NOPT * NV4) + lane;

    // pos/neg bitmasks from int32 labels (lanes 0..15 read one each).
    int lab = (lane < NOPT) ? labels[(size_t)sample * NOPT + lane] : -1;
    const unsigned pos_mask = __ballot_sync(0xffffffffu, (lane < NOPT) && (lab == 1));
    const unsigned neg_mask = __ballot_sync(0xffffffffu, (lane < NOPT) && (lab == 0));

    float acc[NPAIR];
#pragma unroll
    for (int i = 0; i < NPAIR; ++i) acc[i] = 0.0f;

#pragma unroll 1
    for (int c = 0; c < NV4 / 32; ++c) {
        float4 x[NOPT];
#pragma unroll
        for (int n = 0; n < NOPT; ++n)
            x[n] = __ldcs(base + n * NV4 + c * 32);   // LDG.128, coalesced, streaming
#pragma unroll
        for (int n = 0; n < NOPT; ++n) {
#pragma unroll
            for (int m = n; m < NOPT; ++m) {
                float v = acc[triu_idx(n, m)];
                v = fmaf(x[n].x, x[m].x, v);
                v = fmaf(x[n].y, x[m].y, v);
                v = fmaf(x[n].z, x[m].z, v);
                v = fmaf(x[n].w, x[m].w, v);
                acc[triu_idx(n, m)] = v;
            }
        }
    }

    // Cross-lane reduction, two pairs per butterfly tree:
    // lanes 0-15 carry pair i, lanes 16-31 carry pair i+68.
    __shared__ float ssum[4][NPAIR];
    float* s = ssum[warp];
#pragma unroll
    for (int i = 0; i < HPAIR; ++i) {
        float a = acc[i], b = acc[i + HPAIR];
        float keep = (lane < 16) ? a : b;
        float send = (lane < 16) ? b : a;
        float w = keep + __shfl_xor_sync(0xffffffffu, send, 16);
        w += __shfl_xor_sync(0xffffffffu, w, 8);
        w += __shfl_xor_sync(0xffffffffu, w, 4);
        w += __shfl_xor_sync(0xffffffffu, w, 2);
        w += __shfl_xor_sync(0xffffffffu, w, 1);
        if (lane == 0)  s[i] = w;
        if (lane == 16) s[i + HPAIR] = w;
    }
    __syncwarp();

    // Inverse norms: lane m computes its own, then broadcast-gather all 16.
    float inv_own = 0.0f;
    if (lane < NOPT) {
        float nrm = sqrtf(s[triu_idx(lane, lane)]);
        inv_own = 1.0f / fmaxf(nrm, 1e-12f);
    }
    float inv[NOPT];
#pragma unroll
    for (int m = 0; m < NOPT; ++m)
        inv[m] = __shfl_sync(0xffffffffu, inv_own, m);

    const bool valid = (pos_mask != 0u) && (neg_mask != 0u);

    // Lane n handles row n: max cosine sim against negative columns.
    float triplet = 0.0f;
    if (lane < NOPT && valid && ((pos_mask >> lane) & 1u)) {
        float mx = NEG_INF;
#pragma unroll
        for (int m = 0; m < NOPT; ++m) {
            if ((neg_mask >> m) & 1u) {
                int a = lane < m ? lane : m;
                int b = lane < m ? m : lane;
                float sim = s[triu_idx(a, b)] * inv[lane] * inv[m];
                mx = fmaxf(mx, sim);
            }
        }
        triplet = fmaxf(mx + MARGIN, 0.0f);
    }

    // Warp-sum triplet contributions.
    float tsum = triplet;
    tsum += __shfl_xor_sync(0xffffffffu, tsum, 16);
    tsum += __shfl_xor_sync(0xffffffffu, tsum, 8);
    tsum += __shfl_xor_sync(0xffffffffu, tsum, 4);
    tsum += __shfl_xor_sync(0xffffffffu, tsum, 2);
    tsum += __shfl_xor_sync(0xffffffffu, tsum, 1);

    if (lane == 0) {
        g_loss[sample] = tsum;
        g_cnt[sample]  = valid ? (float)__popc(pos_mask) : 0.0f;
    }
}

// Fixed-tree deterministic global reduction: out = sum(loss) / max(sum(count), 1)
__global__ void reduce_kernel(float* __restrict__ out)
{
    __shared__ float sl[256];
    __shared__ float sc[256];
    const int t = threadIdx.x;
    float ls = 0.0f, cs = 0.0f;
    for (int i = t; i < NSAMP; i += 256) {
        ls += g_loss[i];
        cs += g_cnt[i];
    }
    sl[t] = ls; sc[t] = cs;
    __syncthreads();
    for (int stride = 128; stride > 0; stride >>= 1) {
        if (t < stride) { sl[t] += sl[t + stride]; sc[t] += sc[t + stride]; }
        __syncthreads();
    }
    if (t == 0)
        out[0] = sl[0] / fmaxf(sc[0], 1.0f);
}

extern "C" void kernel_launch(void* const* d_in, const int* in_sizes, int n_in,
                              void* d_out, int out_size)
{
    const float4* emb = (const float4*)d_in[0];  // [8192, 16, 768] float32
    const int* labels = (const int*)d_in[1];     // [8192, 16] int32 (verified R5/R9)
    float* out = (float*)d_out;                  // scalar float32

    (void)in_sizes; (void)n_in; (void)out_size;

    gram_kernel<<<NSAMP / 4, 128>>>(emb, labels);
    reduce_kernel<<<1, 256>>>(out);
}

// round 11
// speedup vs baseline: 1.0036x; 1.0036x over previous
#include <cuda_runtime.h>

#define NSAMP 8192
#define NOPT  16
#define DIM   768
#define NV2   (DIM / 2)        // 384 float2 per row
#define CHUNKS (NV2 / 32)      // 12 chunks of 32 float2 (64 floats) per lane-cycle
#define NPAIR 136              // 16*17/2 upper-triangular incl. diagonal
#define HPAIR 68               // NPAIR / 2
#define MARGIN 0.3f
#define NEG_INF -1e9f

// Deterministic per-sample scratch (no device-side allocation allowed).
__device__ float g_loss[NSAMP];
__device__ float g_cnt[NSAMP];
__device__ unsigned g_ticket;   // zero-initialized; reset by the finishing block

__device__ __forceinline__ constexpr int triu_idx(int n, int m) {
    // n <= m required. Pairs of row n start at 16n - n(n-1)/2.
    return n * 16 - (n * (n - 1)) / 2 + (m - n);
}

// One warp per sample. Lane l owns float2 index l + 32c (c = 0..11).
// Double-buffered: loads for chunk c+1 issue before the FMAs of chunk c,
// so DRAM latency is hidden inside the warp itself (occupancy-independent).
__global__ __launch_bounds__(128, 2)
void gram_kernel(const float2* __restrict__ emb, const int* __restrict__ labels,
                 float* __restrict__ out)
{
    const int warp = threadIdx.x >> 5;
    const int lane = threadIdx.x & 31;
    const int sample = blockIdx.x * 4 + warp;

    const float2* p = emb + (size_t)sample * (NOPT * NV2) + lane;

    // pos/neg bitmasks from int32 labels (lanes 0..15 read one each).
    int lab = (lane < NOPT) ? labels[(size_t)sample * NOPT + lane] : -1;
    const unsigned pos_mask = __ballot_sync(0xffffffffu, (lane < NOPT) && (lab == 1));
    const unsigned neg_mask = __ballot_sync(0xffffffffu, (lane < NOPT) && (lab == 0));

    float acc[NPAIR];
#pragma unroll
    for (int i = 0; i < NPAIR; ++i) acc[i] = 0.0f;

    float2 xa[NOPT], xb[NOPT];
#pragma unroll
    for (int n = 0; n < NOPT; ++n)
        xa[n] = __ldcs(p + n * NV2);                 // prefetch chunk 0

#pragma unroll 1
    for (int c = 0; c < CHUNKS; c += 2) {
        // Prefetch chunk c+1 (always exists: CHUNKS even, c <= CHUNKS-2).
        const float2* pb = p + (c + 1) * 32;
#pragma unroll
        for (int n = 0; n < NOPT; ++n)
            xb[n] = __ldcs(pb + n * NV2);

        // Compute chunk c from xa.
#pragma unroll
        for (int n = 0; n < NOPT; ++n) {
#pragma unroll
            for (int m = n; m < NOPT; ++m) {
                float v = acc[triu_idx(n, m)];
                v = fmaf(xa[n].x, xa[m].x, v);
                v = fmaf(xa[n].y, xa[m].y, v);
                acc[triu_idx(n, m)] = v;
            }
        }

        // Prefetch chunk c+2 (skipped only on the last iteration).
        if (c + 2 < CHUNKS) {
            const float2* pa = p + (c + 2) * 32;
#pragma unroll
            for (int n = 0; n < NOPT; ++n)
                xa[n] = __ldcs(pa + n * NV2);
        }

        // Compute chunk c+1 from xb.
#pragma unroll
        for (int n = 0; n < NOPT; ++n) {
#pragma unroll
            for (int m = n; m < NOPT; ++m) {
                float v = acc[triu_idx(n, m)];
                v = fmaf(xb[n].x, xb[m].x, v);
                v = fmaf(xb[n].y, xb[m].y, v);
                acc[triu_idx(n, m)] = v;
            }
        }
    }

    // Cross-lane reduction, two pairs per butterfly tree:
    // lanes 0-15 carry pair i, lanes 16-31 carry pair i+68.
    __shared__ float ssum[4][NPAIR];
    float* s = ssum[warp];
#pragma unroll
    for (int i = 0; i < HPAIR; ++i) {
        float a = acc[i], b = acc[i + HPAIR];
        float keep = (lane < 16) ? a : b;
        float send = (lane < 16) ? b : a;
        float w = keep + __shfl_xor_sync(0xffffffffu, send, 16);
        w += __shfl_xor_sync(0xffffffffu, w, 8);
        w += __shfl_xor_sync(0xffffffffu, w, 4);
        w += __shfl_xor_sync(0xffffffffu, w, 2);
        w += __shfl_xor_sync(0xffffffffu, w, 1);
        if (lane == 0)  s[i] = w;
        if (lane == 16) s[i + HPAIR] = w;
    }
    __syncwarp();

    // Inverse norms: lane m computes its own, then broadcast-gather all 16.
    float inv_own = 0.0f;
    if (lane < NOPT) {
        float nrm = sqrtf(s[triu_idx(lane, lane)]);
        inv_own = 1.0f / fmaxf(nrm, 1e-12f);
    }
    float inv[NOPT];
#pragma unroll
    for (int m = 0; m < NOPT; ++m)
        inv[m] = __shfl_sync(0xffffffffu, inv_own, m);

    const bool valid = (pos_mask != 0u) && (neg_mask != 0u);

    // Lane n handles row n: max cosine sim against negative columns.
    float triplet = 0.0f;
    if (lane < NOPT && valid && ((pos_mask >> lane) & 1u)) {
        float mx = NEG_INF;
#pragma unroll
        for (int m = 0; m < NOPT; ++m) {
            if ((neg_mask >> m) & 1u) {
                int a = lane < m ? lane : m;
                int b = lane < m ? m : lane;
                float sim = s[triu_idx(a, b)] * inv[lane] * inv[m];
                mx = fmaxf(mx, sim);
            }
        }
        triplet = fmaxf(mx + MARGIN, 0.0f);
    }

    // Warp-sum triplet contributions.
    float tsum = triplet;
    tsum += __shfl_xor_sync(0xffffffffu, tsum, 16);
    tsum += __shfl_xor_sync(0xffffffffu, tsum, 8);
    tsum += __shfl_xor_sync(0xffffffffu, tsum, 4);
    tsum += __shfl_xor_sync(0xffffffffu, tsum, 2);
    tsum += __shfl_xor_sync(0xffffffffu, tsum, 1);

    if (lane == 0) {
        g_loss[sample] = tsum;
        g_cnt[sample]  = valid ? (float)__popc(pos_mask) : 0.0f;
    }

    // ── Fused deterministic final reduction (last-block pattern) ──
    // The reduction is a fixed tree over g_loss/g_cnt, so the result does not
    // depend on WHICH block finishes last. Ticket reset keeps graph replays
    // deterministic.
    __syncthreads();                       // all warps' g_loss/g_cnt stores issued
    __shared__ unsigned s_ticket;
    if (threadIdx.x == 0) {
        __threadfence();                   // publish this block's results
        s_ticket = atomicAdd(&g_ticket, 1u);
    }
    __syncthreads();
    if (s_ticket == gridDim.x - 1) {
        __threadfence();                   // acquire all blocks' results
        __shared__ float sl[128], sc[128];
        const int t = threadIdx.x;
        float ls = 0.0f, cs = 0.0f;
        for (int i = t; i < NSAMP; i += 128) {
            ls += g_loss[i];
            cs += g_cnt[i];
        }
        sl[t] = ls; sc[t] = cs;
        __syncthreads();
#pragma unroll
        for (int stride = 64; stride > 0; stride >>= 1) {
            if (t < stride) { sl[t] += sl[t + stride]; sc[t] += sc[t + stride]; }
            __syncthreads();
        }
        if (t == 0) {
            out[0] = sl[0] / fmaxf(sc[0], 1.0f);
            g_ticket = 0;                  // reset for next graph replay
        }
    }
}

extern "C" void kernel_launch(void* const* d_in, const int* in_sizes, int n_in,
                              void* d_out, int out_size)
{
    const float2* emb = (const float2*)d_in[0];  // [8192, 16, 768] float32
    const int* labels = (const int*)d_in[1];     // [8192, 16] int32 (verified R5/R9)
    float* out = (float*)d_out;                  // scalar float32

    (void)in_sizes; (void)n_in; (void)out_size;

    gram_kernel<<<NSAMP / 4, 128>>>(emb, labels, out);
}